// round 10
// baseline (speedup 1.0000x reference)
#include <cuda_runtime.h>
#include <cuda_bf16.h>
#include <math.h>

#define B 32
#define L 256
#define D 512
#define MAX_LEN 2048                     // L * MAX_DUR(8)
#define ROWS_PB 32                       // output rows per block
#define BLOCKS_PER_BATCH (MAX_LEN / ROWS_PB)   // 64
#define F4_PER_ROW (D / 4)               // 128
#define ELEMS_PB (ROWS_PB * F4_PER_ROW)  // 4096 float4 per block
#define ELEMS_PT (ELEMS_PB / 256)        // 16 float4 per thread

// ---------------------------------------------------------------------------
// Fused length-regulator (round-6 structure + idempotent zero-fill).
// Per block: recompute per-batch scan, derive source index for its 32 output
// rows, then flat expand-copy of 16 independent float4 pairs per thread.
//   idx >= 0 : gather + streaming store (.cs) -> evict-first write stream
//   idx <  0 : READ current value; store zero only if nonzero. After the
//              first replay these ~67 MB of lines are clean zeros, stay
//              L2-resident (67 + 16.8 att_out < 126 MB L2), and generate
//              ZERO DRAM traffic in the graph-replay steady state.
// Output is a pure function of inputs from any initial d_out state.
// Grid = 2048 blocks x 256 threads.
// ---------------------------------------------------------------------------
__global__ void __launch_bounds__(256)
lr_fused_kernel(const float* __restrict__ att_out,
                const float* __restrict__ duration,
                const void*  __restrict__ alpha_ptr,
                float* __restrict__ out)
{
    const int b        = blockIdx.x / BLOCKS_PER_BATCH;
    const int row_base = (blockIdx.x % BLOCKS_PER_BATCH) * ROWS_PB;
    const int t    = threadIdx.x;       // 0..255
    const int lane = t & 31;
    const int wid  = t >> 5;            // 0..7

    // --- resolve alpha (int32 or float32, bit-sniffed) ---
    int   ab = *(const int*)alpha_ptr;
    float af = __int_as_float(ab);
    float alpha = (fabsf(af) >= 1e-30f && fabsf(af) <= 1e30f) ? af : (float)ab;

    // --- round (rintf = round-half-even, matches jnp.round) ---
    int r = (int)rintf(__ldg(&duration[b * L + t]) * alpha);

    // --- inclusive scan over 256 values ---
    int v = r;
    #pragma unroll
    for (int off = 1; off < 32; off <<= 1) {
        int n = __shfl_up_sync(0xffffffffu, v, off);
        if (lane >= off) v += n;
    }
    __shared__ int warp_tot[8];
    __shared__ int warp_pre[8];
    if (lane == 31) warp_tot[wid] = v;
    __syncthreads();
    if (t < 8) {
        int wv = warp_tot[t];
        #pragma unroll
        for (int off = 1; off < 8; off <<= 1) {
            int n = __shfl_up_sync(0xffu, wv, off);
            if (t >= off) wv += n;
        }
        warp_pre[t] = wv;
    }
    __syncthreads();
    int csum = v + (wid > 0 ? warp_pre[wid - 1] : 0);

    __shared__ int s_csum[L];
    s_csum[t] = csum;
    __syncthreads();

    const int total = s_csum[L - 1];

    // --- per-row source index for this block's 32 rows (-1 = masked) ---
    __shared__ int s_idx[ROWS_PB];
    if (t < ROWS_PB) {
        int pos = row_base + t;
        int outi;
        if (pos >= total) {
            outi = -1;
        } else {
            int lo = 0, hi = L;             // first i with csum[i] > pos
            while (lo < hi) {
                int mid = (lo + hi) >> 1;
                if (s_csum[mid] > pos) hi = mid; else lo = mid + 1;
            }
            outi = lo < (L - 1) ? lo : (L - 1);
        }
        s_idx[t] = outi;
    }
    __syncthreads();

    // --- flat expand copy: 16 independent float4 ops per thread ---
    const float4* __restrict__ src = (const float4*)(att_out + (size_t)b * L * D);
    float4* __restrict__ dst =
        (float4*)(out + ((size_t)b * MAX_LEN + row_base) * D);

    #pragma unroll
    for (int k = 0; k < ELEMS_PT; k++) {
        int e   = k * 256 + t;
        int row = e >> 7;
        int col = e & (F4_PER_ROW - 1);
        int idx = s_idx[row];               // warp-uniform
        if (idx >= 0) {
            float4 val = __ldg(src + (size_t)idx * F4_PER_ROW + col);
            __stcs(dst + e, val);           // streaming write
        } else {
            // idempotent zero-fill: skip the store when already zero so the
            // line stays CLEAN and L2-resident across graph replays
            float4 cur = dst[e];            // cached read (wants residency)
            if (cur.x != 0.f || cur.y != 0.f || cur.z != 0.f || cur.w != 0.f)
                dst[e] = make_float4(0.f, 0.f, 0.f, 0.f);
        }
    }
}

extern "C" void kernel_launch(void* const* d_in, const int* in_sizes, int n_in,
                              void* d_out, int out_size)
{
    const float* att_out  = (const float*)d_in[0];
    const float* duration = (const float*)d_in[1];
    const void*  alpha    = d_in[2];

    lr_fused_kernel<<<B * BLOCKS_PER_BATCH, 256>>>(att_out, duration, alpha,
                                                   (float*)d_out);
}

// round 11
// speedup vs baseline: 1.4141x; 1.4141x over previous
#include <cuda_runtime.h>
#include <cuda_bf16.h>
#include <math.h>

#define B 32
#define L 256
#define D 512
#define MAX_LEN 2048                     // L * MAX_DUR(8)
#define THREADS 512
#define ROWS_PB 64                       // output rows per block
#define BLOCKS_PER_BATCH (MAX_LEN / ROWS_PB)   // 32
#define F4_PER_ROW (D / 4)               // 128
#define ELEMS_PB (ROWS_PB * F4_PER_ROW)  // 8192 float4 per block
#define ELEMS_PT (ELEMS_PB / THREADS)    // 16 float4 per thread

// ---------------------------------------------------------------------------
// Fused length-regulator (round-6 champion copy loop, amortized preamble).
// 1024 blocks x 512 threads: each block recomputes the per-batch scan once
// (half as many redundant scans as the 2048-block version), derives source
// indices for its 64 output rows, then does a flat expand-copy of 16
// independent float4 LDG->STG.cs pairs per thread. All-streaming stores:
// rounds 7/9/10 proved any L2-retention scheme for the 134MB output regresses
// the replay loop; the kernel sits at the HBM write-drain floor (~5.4 TB/s).
// ---------------------------------------------------------------------------
__global__ void __launch_bounds__(THREADS)
lr_fused_kernel(const float* __restrict__ att_out,
                const float* __restrict__ duration,
                const void*  __restrict__ alpha_ptr,
                float* __restrict__ out)
{
    const int b        = blockIdx.x / BLOCKS_PER_BATCH;
    const int row_base = (blockIdx.x % BLOCKS_PER_BATCH) * ROWS_PB;
    const int t    = threadIdx.x;       // 0..511
    const int lane = t & 31;
    const int wid  = t >> 5;            // 0..15

    __shared__ int warp_tot[8];
    __shared__ int warp_pre[8];
    __shared__ int s_csum[L];
    __shared__ int s_idx[ROWS_PB];

    // --- scan preamble: only threads 0..255 participate ---
    if (t < L) {
        // resolve alpha (int32 or float32, bit-sniffed)
        int   ab = *(const int*)alpha_ptr;
        float af = __int_as_float(ab);
        float alpha = (fabsf(af) >= 1e-30f && fabsf(af) <= 1e30f) ? af : (float)ab;

        // round (rintf = round-half-even, matches jnp.round)
        int r = (int)rintf(__ldg(&duration[b * L + t]) * alpha);

        // inclusive warp scan
        int v = r;
        #pragma unroll
        for (int off = 1; off < 32; off <<= 1) {
            int n = __shfl_up_sync(0xffffffffu, v, off);
            if (lane >= off) v += n;
        }
        if (lane == 31) warp_tot[wid] = v;
        __syncthreads();
        if (t < 8) {
            int wv = warp_tot[t];
            #pragma unroll
            for (int off = 1; off < 8; off <<= 1) {
                int n = __shfl_up_sync(0xffu, wv, off);
                if (t >= off) wv += n;
            }
            warp_pre[t] = wv;
        }
        __syncthreads();
        s_csum[t] = v + (wid > 0 ? warp_pre[wid - 1] : 0);
    } else {
        __syncthreads();
        __syncthreads();
    }
    __syncthreads();

    const int total = s_csum[L - 1];

    // --- per-row source index for this block's 64 rows (-1 = masked) ---
    if (t < ROWS_PB) {
        int pos = row_base + t;
        int outi;
        if (pos >= total) {
            outi = -1;
        } else {
            int lo = 0, hi = L;             // first i with csum[i] > pos
            while (lo < hi) {
                int mid = (lo + hi) >> 1;
                if (s_csum[mid] > pos) hi = mid; else lo = mid + 1;
            }
            outi = lo < (L - 1) ? lo : (L - 1);
        }
        s_idx[t] = outi;
    }
    __syncthreads();

    // --- flat expand copy: 16 independent float4 copies per thread ---
    const float4* __restrict__ src = (const float4*)(att_out + (size_t)b * L * D);
    float4* __restrict__ dst =
        (float4*)(out + ((size_t)b * MAX_LEN + row_base) * D);
    const float4 zero = make_float4(0.f, 0.f, 0.f, 0.f);

    #pragma unroll
    for (int k = 0; k < ELEMS_PT; k++) {
        int e   = k * THREADS + t;          // 0..8191 within block chunk
        int row = e >> 7;                   // local output row
        int col = e & (F4_PER_ROW - 1);
        int idx = s_idx[row];               // warp-uniform
        float4 val = (idx >= 0)
                   ? __ldg(src + (size_t)idx * F4_PER_ROW + col)
                   : zero;
        __stcs(dst + e, val);               // streaming write (champion policy)
    }
}

extern "C" void kernel_launch(void* const* d_in, const int* in_sizes, int n_in,
                              void* d_out, int out_size)
{
    const float* att_out  = (const float*)d_in[0];
    const float* duration = (const float*)d_in[1];
    const void*  alpha    = d_in[2];

    lr_fused_kernel<<<B * BLOCKS_PER_BATCH, THREADS>>>(att_out, duration, alpha,
                                                       (float*)d_out);
}

// round 14
// speedup vs baseline: 1.4377x; 1.0167x over previous
#include <cuda_runtime.h>
#include <cuda_bf16.h>
#include <math.h>

#define B 32
#define L 256
#define D 512
#define MAX_LEN 2048                     // L * MAX_DUR(8)
#define ROWS_PB 32                       // output rows per block
#define BLOCKS_PER_BATCH (MAX_LEN / ROWS_PB)   // 64
#define F4_PER_ROW (D / 4)               // 128
#define ELEMS_PT 16                      // float4 copies per thread

// ---------------------------------------------------------------------------
// Fused length-regulator — champion configuration (round 6) with minimal
// addressing ALU. 2048 blocks x 256 threads; per block: recompute per-batch
// scan (cheap), derive source index for its 32 output rows, then 16
// independent float4 LDG -> STG.cs pairs per thread. For e = k*256 + t the
// local row is 2k + (t>>7): warp-uniform, compile-time stride -> the old
// per-iteration e/row/col decode collapses to one s_idx load + constant
// offsets. All-streaming stores: the kernel sits at the HBM write-drain
// floor (~5.7 TB/s of mandatory output writes); L2-retention schemes for
// the 134MB output were disproven in rounds 7/9/10.
// ---------------------------------------------------------------------------
__global__ void __launch_bounds__(256)
lr_fused_kernel(const float* __restrict__ att_out,
                const float* __restrict__ duration,
                const void*  __restrict__ alpha_ptr,
                float* __restrict__ out)
{
    const int b        = blockIdx.x / BLOCKS_PER_BATCH;
    const int row_base = (blockIdx.x % BLOCKS_PER_BATCH) * ROWS_PB;
    const int t    = threadIdx.x;       // 0..255
    const int lane = t & 31;
    const int wid  = t >> 5;            // 0..7

    // --- resolve alpha (int32 or float32, bit-sniffed) ---
    int   ab = *(const int*)alpha_ptr;
    float af = __int_as_float(ab);
    float alpha = (fabsf(af) >= 1e-30f && fabsf(af) <= 1e30f) ? af : (float)ab;

    // --- round (rintf = round-half-even, matches jnp.round) ---
    int r = (int)rintf(__ldg(&duration[b * L + t]) * alpha);

    // --- inclusive scan over 256 values ---
    int v = r;
    #pragma unroll
    for (int off = 1; off < 32; off <<= 1) {
        int n = __shfl_up_sync(0xffffffffu, v, off);
        if (lane >= off) v += n;
    }
    __shared__ int warp_tot[8];
    __shared__ int warp_pre[8];
    if (lane == 31) warp_tot[wid] = v;
    __syncthreads();
    if (t < 8) {
        int wv = warp_tot[t];
        #pragma unroll
        for (int off = 1; off < 8; off <<= 1) {
            int n = __shfl_up_sync(0xffu, wv, off);
            if (t >= off) wv += n;
        }
        warp_pre[t] = wv;
    }
    __syncthreads();
    int csum = v + (wid > 0 ? warp_pre[wid - 1] : 0);

    __shared__ int s_csum[L];
    s_csum[t] = csum;
    __syncthreads();

    const int total = s_csum[L - 1];

    // --- per-row source index for this block's 32 rows (-1 = masked) ---
    __shared__ int s_idx[ROWS_PB];
    if (t < ROWS_PB) {
        int pos = row_base + t;
        int outi;
        if (pos >= total) {
            outi = -1;
        } else {
            int lo = 0, hi = L;             // first i with csum[i] > pos
            while (lo < hi) {
                int mid = (lo + hi) >> 1;
                if (s_csum[mid] > pos) hi = mid; else lo = mid + 1;
            }
            outi = lo < (L - 1) ? lo : (L - 1);
        }
        s_idx[t] = outi;
    }
    __syncthreads();

    // --- flat expand copy: 16 independent float4 copies per thread ---
    // e = k*256 + t  =>  local row = 2k + (t>>7), col = t & 127 (constant).
    const int rl  = t >> 7;                 // 0/1
    const int col = t & (F4_PER_ROW - 1);   // float4 column (constant)

    const float4* __restrict__ src =
        (const float4*)(att_out + (size_t)b * L * D) + col;
    float4* __restrict__ dst =
        (float4*)(out + ((size_t)b * MAX_LEN + row_base) * D) + rl * F4_PER_ROW + col;
    const float4 zero = make_float4(0.f, 0.f, 0.f, 0.f);

    #pragma unroll
    for (int k = 0; k < ELEMS_PT; k++) {
        int idx = s_idx[2 * k + rl];        // warp-uniform LDS broadcast
        float4 val = (idx >= 0)
                   ? __ldg(src + (size_t)idx * F4_PER_ROW)
                   : zero;
        __stcs(dst + (size_t)(2 * k) * F4_PER_ROW, val);  // streaming write
    }
}

extern "C" void kernel_launch(void* const* d_in, const int* in_sizes, int n_in,
                              void* d_out, int out_size)
{
    const float* att_out  = (const float*)d_in[0];
    const float* duration = (const float*)d_in[1];
    const void*  alpha    = d_in[2];

    lr_fused_kernel<<<B * BLOCKS_PER_BATCH, 256>>>(att_out, duration, alpha,
                                                   (float*)d_out);
}